// round 7
// baseline (speedup 1.0000x reference)
#include <cuda_runtime.h>
#include <cuda_bf16.h>
#include <cstdint>

// BiGRU: B=64, S=4096, D_in=7, H=128, 2 layers, bidirectional, fp32.
//   k_gx0    : gx0 = x @ Wih0^T + bih0 (both dirs)     -> g_gx [tok][768]
//   k_rec    : per-(batch,dir) recurrence; 768 thr, half-row/thread (6 w/SMSP)
//   k_gemm_tc: gx1 = h1in @ Wih1^T + bih1 via mma.sync bf16 3-term split
//   k_rec    : layer 1
//   k_head   : logits = h1out @ wout^T + bout

#define BB   64
#define SS   4096
#define DIN  7
#define HH   128
#define G3   384
#define NTOK (BB * SS)          // 262144

// ---------------- scratch (device globals; reused across phases) -------------
__device__ float g_gx [ (size_t)NTOK * 768 ];   // gate pre-activations [f384|b384]
__device__ float g_hio[ (size_t)NTOK * 256 ];   // layer in/out hidden  [f128|b128]

// ---------------- f32x2 helpers ----------------------------------------------
__device__ __forceinline__ unsigned long long ffma2(unsigned long long a,
                                                    unsigned long long b,
                                                    unsigned long long c) {
    unsigned long long d;
    asm("fma.rn.f32x2 %0, %1, %2, %3;" : "=l"(d) : "l"(a), "l"(b), "l"(c));
    return d;
}
__device__ __forceinline__ float2 unpk(unsigned long long v) {
    float2 r;
    asm("mov.b64 {%0, %1}, %2;" : "=f"(r.x), "=f"(r.y) : "l"(v));
    return r;
}
__device__ __forceinline__ float sigf(float x) {
    return __fdividef(1.f, 1.f + __expf(-x));
}
__device__ __forceinline__ float tanhfast(float x) {
    return 1.f - __fdividef(2.f, __expf(2.f * x) + 1.f);
}

// ---------------- warp-MMA helpers (baseline PTX, sm_80+) ---------------------
__device__ __forceinline__ uint32_t smem_u32(const void* p) {
    uint32_t a;
    asm("{ .reg .u64 t; cvta.to.shared.u64 t, %1; cvt.u32.u64 %0, t; }"
        : "=r"(a) : "l"(p));
    return a;
}
__device__ __forceinline__ void ldmx4(uint32_t& r0, uint32_t& r1,
                                      uint32_t& r2, uint32_t& r3, uint32_t addr) {
    asm volatile("ldmatrix.sync.aligned.m8n8.x4.shared.b16 {%0,%1,%2,%3}, [%4];"
                 : "=r"(r0), "=r"(r1), "=r"(r2), "=r"(r3) : "r"(addr));
}
__device__ __forceinline__ void mma_bf16(float* d, const uint32_t* a,
                                         const uint32_t* b) {
    asm volatile("mma.sync.aligned.m16n8k16.row.col.f32.bf16.bf16.f32 "
                 "{%0,%1,%2,%3}, {%4,%5,%6,%7}, {%8,%9}, {%0,%1,%2,%3};"
                 : "+f"(d[0]), "+f"(d[1]), "+f"(d[2]), "+f"(d[3])
                 : "r"(a[0]), "r"(a[1]), "r"(a[2]), "r"(a[3]),
                   "r"(b[0]), "r"(b[1]));
}

// ---------------- layer-0 input projection (K=7) ------------------------------
__global__ void k_gx0(const float* __restrict__ x,
                      const float* __restrict__ wf, const float* __restrict__ bf,
                      const float* __restrict__ wb, const float* __restrict__ bb) {
    __shared__ float sx[8 * DIN];
    int j = threadIdx.x;                       // 0..767
    long long token0 = (long long)blockIdx.x * 8;
    int dir = (j >= G3);
    int jj = dir ? j - G3 : j;
    const float* wrow = (dir ? wb : wf) + jj * DIN;
    float w0 = wrow[0], w1 = wrow[1], w2 = wrow[2], w3 = wrow[3];
    float w4 = wrow[4], w5 = wrow[5], w6 = wrow[6];
    float bias = (dir ? bb : bf)[jj];
    if (j < 8 * DIN) sx[j] = x[token0 * DIN + j];
    __syncthreads();
#pragma unroll
    for (int tk = 0; tk < 8; tk++) {
        const float* xs = sx + tk * DIN;
        float v = bias;
        v = fmaf(w0, xs[0], v); v = fmaf(w1, xs[1], v); v = fmaf(w2, xs[2], v);
        v = fmaf(w3, xs[3], v); v = fmaf(w4, xs[4], v); v = fmaf(w5, xs[5], v);
        v = fmaf(w6, xs[6], v);
        g_gx[(token0 + tk) * 768 + j] = v;
    }
}

// ---------------- recurrence: one CTA per (batch, dir), 768 threads -----------
// Thread j: row = j % 384, half = j / 384. Owns 64 weights (32 f32x2 regs),
// 32 FFMA2/step over its h-half (16 LDS.128). Partials -> s_p0/s_p1.
// half-0 folds bhh (+gx for r,z rows) into its partial; gx pipeline lives in
// half-0 threads only (same 12-warp distributed prefetch as the proven r6 ver).
// Gate threads (j<128) combine and update h. 24 warps = 6/SMSP for latency.
__global__ void __launch_bounds__(768, 1) k_rec(
    const float* __restrict__ whh_f, const float* __restrict__ bhh_f,
    const float* __restrict__ whh_b, const float* __restrict__ bhh_b) {
    __shared__ __align__(16) float s_h[HH];
    __shared__ float s_p0[G3];
    __shared__ float s_p1[G3];
    __shared__ float s_xn[HH];

    int j    = threadIdx.x;
    int row  = j & 383;                        // j % 384 (384 = 256+128; use cmp)
    int half = j >= G3;
    row = j - half * G3;

    int b   = blockIdx.x >> 1;
    int dir = blockIdx.x & 1;

    const float* whh  = dir ? whh_b : whh_f;
    const float* bhhp = dir ? bhh_b : bhh_f;

    // weights: row's half of Whh = 64 floats = 32 f32x2 regs
    unsigned long long w[32];
    {
        const unsigned long long* wp =
            (const unsigned long long*)(whh + (size_t)row * HH + half * 64);
#pragma unroll
        for (int i = 0; i < 32; i++) w[i] = wp[i];
    }
    float bhh = half ? 0.f : bhhp[row];        // folded into half-0 partial

    if (j < HH) s_h[j] = 0.f;
    float hreg = 0.f;

    long long tokbase = (long long)b * SS;
    int t0 = dir ? (SS - 1) : 0;
    long long gstr = dir ? -768 : 768;
    long long hstr = dir ? -256 : 256;

    // gx pipeline (half-0 threads only, 2-step prefetch)
    const float* gp = g_gx + (tokbase + t0) * 768 + (long long)dir * G3 + row;
    float*       hp = g_hio + (tokbase + t0) * 256 + (long long)dir * HH + j;
    float gx_n1 = 0.f, gx_n2 = 0.f;
    if (!half) {
        gx_n1 = gp[0];
        gp += gstr;
        gx_n2 = gp[0];
    }
    __syncthreads();

    const ulonglong2* hv = (const ulonglong2*)(s_h + half * 64);

    for (int tt = 0; tt < SS; tt++) {
        float gxv = gx_n1;
        if (!half) {
            gx_n1 = gx_n2;
            gp += gstr;
            if (tt + 2 < SS) gx_n2 = *gp;
        }

        unsigned long long a0 = 0ull, a1 = 0ull;
#pragma unroll
        for (int k = 0; k < 16; k++) {
            ulonglong2 hk = hv[k];              // LDS.128, warp-uniform broadcast
            a0 = ffma2(w[2 * k],     hk.x, a0);
            a1 = ffma2(w[2 * k + 1], hk.y, a1);
        }
        float2 f0 = unpk(a0), f1 = unpk(a1);
        float part = (f0.x + f0.y) + (f1.x + f1.y);

        if (!half) {
            // fold bias; fold gx for r,z rows; stash xn for n rows
            if (row < 2 * HH) {
                s_p0[row] = part + bhh + gxv;
            } else {
                s_p0[row] = part + bhh;
                s_xn[row - 2 * HH] = gxv;
            }
        } else {
            s_p1[row] = part;
        }
        __syncthreads();

        if (j < HH) {
            float r  = sigf(s_p0[j]          + s_p1[j]);
            float z  = sigf(s_p0[HH + j]     + s_p1[HH + j]);
            float hn =      s_p0[2 * HH + j] + s_p1[2 * HH + j];
            float n  = tanhfast(fmaf(r, hn, s_xn[j]));
            hreg = fmaf(z, hreg - n, n);         // (1-z)*n + z*h
            s_h[j] = hreg;
            *hp = hreg;
            hp += hstr;
        }
        __syncthreads();
    }
}

// ---------------- layer-1 GEMM via mma.sync (bf16 3-term split) ----------------
// C[262144 x 768] = A[262144 x 256] * W[768 x 256]^T + bias
// CTA tile M=128, N=256 (grid.y = 3), 8 warps as 2x4 (warp tile 64x64),
// K in 16 chunks of 16. fp32 -> bf16 hi/lo split done during smem fill.
#define ASTR 24          // smem row stride in bf16 elems (48B: aligned, no conflicts)

__global__ void __launch_bounds__(256, 1) k_gemm_tc(
    const float* __restrict__ Wf, const float* __restrict__ bf,
    const float* __restrict__ Wb, const float* __restrict__ bb) {
    __shared__ __align__(16) __nv_bfloat16 Ah[128][ASTR];
    __shared__ __align__(16) __nv_bfloat16 Al[128][ASTR];
    __shared__ __align__(16) __nv_bfloat16 Bh[256][ASTR];
    __shared__ __align__(16) __nv_bfloat16 Bl[256][ASTR];

    int tid = threadIdx.x, wid = tid >> 5, lane = tid & 31;
    long long m0 = (long long)blockIdx.x * 128;
    int n0 = blockIdx.y * 256;
    int wm = wid >> 2, wn = wid & 3;             // warp 64x64 tile at (wm*64, wn*64)

    uint32_t aoff = (uint32_t)(((wm * 64 + (lane & 15)) * ASTR + (lane >> 4) * 8) * 2);
    uint32_t boff = (uint32_t)(((wn * 64 + (lane & 7) + ((lane >> 4) << 3)) * ASTR
                                + ((lane >> 3) & 1) * 8) * 2);
    uint32_t ah_a = smem_u32(Ah) + aoff, al_a = smem_u32(Al) + aoff;
    uint32_t bh_a = smem_u32(Bh) + boff, bl_a = smem_u32(Bl) + boff;

    float acc[4][8][4];
#pragma unroll
    for (int i = 0; i < 4; i++)
#pragma unroll
        for (int j = 0; j < 8; j++)
#pragma unroll
            for (int q = 0; q < 4; q++) acc[i][j][q] = 0.f;

    float4 pA[2], pB[4];
#pragma unroll
    for (int i = 0; i < 2; i++) {
        int task = tid + i * 256, row = task >> 2, c4 = task & 3;
        pA[i] = *(const float4*)(g_hio + (m0 + row) * 256 + c4 * 4);
    }
#pragma unroll
    for (int i = 0; i < 4; i++) {
        int task = tid + i * 256, row = task >> 2, c4 = task & 3;
        int n = n0 + row;
        const float* src = (n < 384) ? (Wf + (size_t)n * 256)
                                     : (Wb + (size_t)(n - 384) * 256);
        pB[i] = *(const float4*)(src + c4 * 4);
    }

    for (int ck = 0; ck < 16; ck++) {
#pragma unroll
        for (int i = 0; i < 2; i++) {
            int task = tid + i * 256, row = task >> 2, c4 = task & 3;
            float4 v = pA[i];
            __nv_bfloat16 hx = __float2bfloat16(v.x), hy = __float2bfloat16(v.y);
            __nv_bfloat16 hz = __float2bfloat16(v.z), hw = __float2bfloat16(v.w);
            __nv_bfloat162 h01 = __halves2bfloat162(hx, hy);
            __nv_bfloat162 h23 = __halves2bfloat162(hz, hw);
            __nv_bfloat162 l01 = __halves2bfloat162(
                __float2bfloat16(v.x - __bfloat162float(hx)),
                __float2bfloat16(v.y - __bfloat162float(hy)));
            __nv_bfloat162 l23 = __halves2bfloat162(
                __float2bfloat16(v.z - __bfloat162float(hz)),
                __float2bfloat16(v.w - __bfloat162float(hw)));
            *(uint2*)&Ah[row][c4 * 4] = make_uint2(*(uint32_t*)&h01, *(uint32_t*)&h23);
            *(uint2*)&Al[row][c4 * 4] = make_uint2(*(uint32_t*)&l01, *(uint32_t*)&l23);
        }
#pragma unroll
        for (int i = 0; i < 4; i++) {
            int task = tid + i * 256, row = task >> 2, c4 = task & 3;
            float4 v = pB[i];
            __nv_bfloat16 hx = __float2bfloat16(v.x), hy = __float2bfloat16(v.y);
            __nv_bfloat16 hz = __float2bfloat16(v.z), hw = __float2bfloat16(v.w);
            __nv_bfloat162 h01 = __halves2bfloat162(hx, hy);
            __nv_bfloat162 h23 = __halves2bfloat162(hz, hw);
            __nv_bfloat162 l01 = __halves2bfloat162(
                __float2bfloat16(v.x - __bfloat162float(hx)),
                __float2bfloat16(v.y - __bfloat162float(hy)));
            __nv_bfloat162 l23 = __halves2bfloat162(
                __float2bfloat16(v.z - __bfloat162float(hz)),
                __float2bfloat16(v.w - __bfloat162float(hw)));
            *(uint2*)&Bh[row][c4 * 4] = make_uint2(*(uint32_t*)&h01, *(uint32_t*)&h23);
            *(uint2*)&Bl[row][c4 * 4] = make_uint2(*(uint32_t*)&l01, *(uint32_t*)&l23);
        }
        __syncthreads();

        if (ck + 1 < 16) {
            int kc = (ck + 1) * 16;
#pragma unroll
            for (int i = 0; i < 2; i++) {
                int task = tid + i * 256, row = task >> 2, c4 = task & 3;
                pA[i] = *(const float4*)(g_hio + (m0 + row) * 256 + kc + c4 * 4);
            }
#pragma unroll
            for (int i = 0; i < 4; i++) {
                int task = tid + i * 256, row = task >> 2, c4 = task & 3;
                int n = n0 + row;
                const float* src = (n < 384) ? (Wf + (size_t)n * 256)
                                             : (Wb + (size_t)(n - 384) * 256);
                pB[i] = *(const float4*)(src + kc + c4 * 4);
            }
        }

#pragma unroll
        for (int term = 0; term < 3; term++) {
            uint32_t aAddr = (term == 2) ? al_a : ah_a;
            uint32_t bAddr = (term == 1) ? bl_a : bh_a;
            uint32_t afr[4][4];
#pragma unroll
            for (int mf = 0; mf < 4; mf++)
                ldmx4(afr[mf][0], afr[mf][1], afr[mf][2], afr[mf][3],
                      aAddr + mf * (16 * ASTR * 2));
            uint32_t bfr[8][2];
#pragma unroll
            for (int p = 0; p < 4; p++) {
                uint32_t r0, r1, r2, r3;
                ldmx4(r0, r1, r2, r3, bAddr + p * (16 * ASTR * 2));
                bfr[2 * p][0] = r0; bfr[2 * p][1] = r1;
                bfr[2 * p + 1][0] = r2; bfr[2 * p + 1][1] = r3;
            }
#pragma unroll
            for (int mf = 0; mf < 4; mf++)
#pragma unroll
                for (int nf = 0; nf < 8; nf++)
                    mma_bf16(acc[mf][nf], afr[mf], bfr[nf]);
        }
        __syncthreads();
    }

    int g = lane >> 2, c2 = (lane & 3) * 2;
    float bias2[8][2];
#pragma unroll
    for (int nf = 0; nf < 8; nf++) {
        int col = n0 + wn * 64 + nf * 8 + c2;
        bias2[nf][0] = (col < 384) ? bf[col] : bb[col - 384];
        bias2[nf][1] = (col + 1 < 384) ? bf[col + 1] : bb[col + 1 - 384];
    }
#pragma unroll
    for (int mf = 0; mf < 4; mf++) {
        long long r0 = m0 + wm * 64 + mf * 16 + g;
#pragma unroll
        for (int nf = 0; nf < 8; nf++) {
            int col = n0 + wn * 64 + nf * 8 + c2;
            *(float2*)&g_gx[r0 * 768 + col] =
                make_float2(acc[mf][nf][0] + bias2[nf][0],
                            acc[mf][nf][1] + bias2[nf][1]);
            *(float2*)&g_gx[(r0 + 8) * 768 + col] =
                make_float2(acc[mf][nf][2] + bias2[nf][0],
                            acc[mf][nf][3] + bias2[nf][1]);
        }
    }
}

// ---------------- output head: logits = h1out @ wout^T + bout -----------------
__global__ void k_head(const float* __restrict__ wout,
                       const float* __restrict__ bout,
                       float* __restrict__ out) {
    int warp = threadIdx.x >> 5, lane = threadIdx.x & 31;
    long long token = (long long)blockIdx.x * 8 + warp;
    const float* hrow = g_hio + token * 256;
    float acc = 0.f;
#pragma unroll
    for (int i = 0; i < 8; i++) {
        int c = lane + i * 32;
        acc = fmaf(hrow[c], wout[c], acc);
    }
#pragma unroll
    for (int off = 16; off; off >>= 1)
        acc += __shfl_xor_sync(0xffffffffu, acc, off);
    if (lane == 0) out[token] = acc + bout[0];
}

// ---------------- launch ------------------------------------------------------
extern "C" void kernel_launch(void* const* d_in, const int* in_sizes, int n_in,
                              void* d_out, int out_size) {
    const float* x     = (const float*)d_in[0];
    const float* wih0f = (const float*)d_in[1];
    const float* whh0f = (const float*)d_in[2];
    const float* bih0f = (const float*)d_in[3];
    const float* bhh0f = (const float*)d_in[4];
    const float* wih0b = (const float*)d_in[5];
    const float* whh0b = (const float*)d_in[6];
    const float* bih0b = (const float*)d_in[7];
    const float* bhh0b = (const float*)d_in[8];
    const float* wih1f = (const float*)d_in[9];
    const float* whh1f = (const float*)d_in[10];
    const float* bih1f = (const float*)d_in[11];
    const float* bhh1f = (const float*)d_in[12];
    const float* wih1b = (const float*)d_in[13];
    const float* whh1b = (const float*)d_in[14];
    const float* bih1b = (const float*)d_in[15];
    const float* bhh1b = (const float*)d_in[16];
    const float* wout  = (const float*)d_in[17];
    const float* bout  = (const float*)d_in[18];
    float* out = (float*)d_out;

    k_gx0    <<<NTOK / 8, 768>>>(x, wih0f, bih0f, wih0b, bih0b);
    k_rec    <<<128, 768>>>(whh0f, bhh0f, whh0b, bhh0b);
    k_gemm_tc<<<dim3(2048, 3), 256>>>(wih1f, bih1f, wih1b, bih1b);
    k_rec    <<<128, 768>>>(whh1f, bhh1f, whh1b, bhh1b);
    k_head   <<<NTOK / 8, 256>>>(wout, bout, out);
}

// round 8
// speedup vs baseline: 2.3998x; 2.3998x over previous
#include <cuda_runtime.h>
#include <cuda_bf16.h>
#include <cstdint>

// BiGRU: B=64, S=4096, D_in=7, H=128, 2 layers, bidirectional, fp32.
//   k_gx0    : gx0 = x @ Wih0^T + bih0 (both dirs)     -> g_gx [tok][768]
//   k_rec    : per-(batch,dir) recurrence (round-6 validated version)
//   k_gemm_tc: gx1 = h1in @ Wih1^T + bih1, mma.sync bf16 3-term split,
//              double-buffered smem (1 barrier/chunk)
//   k_rec    : layer 1
//   k_head   : logits = h1out @ wout^T + bout

#define BB   64
#define SS   4096
#define DIN  7
#define HH   128
#define G3   384
#define NTOK (BB * SS)          // 262144

// ---------------- scratch (device globals; reused across phases) -------------
__device__ float g_gx [ (size_t)NTOK * 768 ];   // gate pre-activations [f384|b384]
__device__ float g_hio[ (size_t)NTOK * 256 ];   // layer in/out hidden  [f128|b128]

// ---------------- f32x2 helpers ----------------------------------------------
__device__ __forceinline__ unsigned long long ffma2(unsigned long long a,
                                                    unsigned long long b,
                                                    unsigned long long c) {
    unsigned long long d;
    asm("fma.rn.f32x2 %0, %1, %2, %3;" : "=l"(d) : "l"(a), "l"(b), "l"(c));
    return d;
}
__device__ __forceinline__ float2 unpk(unsigned long long v) {
    float2 r;
    asm("mov.b64 {%0, %1}, %2;" : "=f"(r.x), "=f"(r.y) : "l"(v));
    return r;
}
__device__ __forceinline__ float sigf(float x) {
    return __fdividef(1.f, 1.f + __expf(-x));
}
__device__ __forceinline__ float tanhfast(float x) {
    return 1.f - __fdividef(2.f, __expf(2.f * x) + 1.f);
}

// ---------------- warp-MMA helpers (baseline PTX, sm_80+) ---------------------
__device__ __forceinline__ uint32_t smem_u32(const void* p) {
    uint32_t a;
    asm("{ .reg .u64 t; cvta.to.shared.u64 t, %1; cvt.u32.u64 %0, t; }"
        : "=r"(a) : "l"(p));
    return a;
}
__device__ __forceinline__ void ldmx4(uint32_t& r0, uint32_t& r1,
                                      uint32_t& r2, uint32_t& r3, uint32_t addr) {
    asm volatile("ldmatrix.sync.aligned.m8n8.x4.shared.b16 {%0,%1,%2,%3}, [%4];"
                 : "=r"(r0), "=r"(r1), "=r"(r2), "=r"(r3) : "r"(addr));
}
__device__ __forceinline__ void mma_bf16(float* d, const uint32_t* a,
                                         const uint32_t* b) {
    asm volatile("mma.sync.aligned.m16n8k16.row.col.f32.bf16.bf16.f32 "
                 "{%0,%1,%2,%3}, {%4,%5,%6,%7}, {%8,%9}, {%0,%1,%2,%3};"
                 : "+f"(d[0]), "+f"(d[1]), "+f"(d[2]), "+f"(d[3])
                 : "r"(a[0]), "r"(a[1]), "r"(a[2]), "r"(a[3]),
                   "r"(b[0]), "r"(b[1]));
}

// ---------------- layer-0 input projection (K=7) ------------------------------
__global__ void k_gx0(const float* __restrict__ x,
                      const float* __restrict__ wf, const float* __restrict__ bf,
                      const float* __restrict__ wb, const float* __restrict__ bb) {
    __shared__ float sx[8 * DIN];
    int j = threadIdx.x;                       // 0..767
    long long token0 = (long long)blockIdx.x * 8;
    int dir = (j >= G3);
    int jj = dir ? j - G3 : j;
    const float* wrow = (dir ? wb : wf) + jj * DIN;
    float w0 = wrow[0], w1 = wrow[1], w2 = wrow[2], w3 = wrow[3];
    float w4 = wrow[4], w5 = wrow[5], w6 = wrow[6];
    float bias = (dir ? bb : bf)[jj];
    if (j < 8 * DIN) sx[j] = x[token0 * DIN + j];
    __syncthreads();
#pragma unroll
    for (int tk = 0; tk < 8; tk++) {
        const float* xs = sx + tk * DIN;
        float v = bias;
        v = fmaf(w0, xs[0], v); v = fmaf(w1, xs[1], v); v = fmaf(w2, xs[2], v);
        v = fmaf(w3, xs[3], v); v = fmaf(w4, xs[4], v); v = fmaf(w5, xs[5], v);
        v = fmaf(w6, xs[6], v);
        g_gx[(token0 + tk) * 768 + j] = v;
    }
}

// ---------------- recurrence (round-6 validated: 384 thr, 168 regs) -----------
__global__ void __launch_bounds__(384, 1) k_rec(
    const float* __restrict__ whh_f, const float* __restrict__ bhh_f,
    const float* __restrict__ whh_b, const float* __restrict__ bhh_b) {
    __shared__ __align__(16) float s_h[HH];
    __shared__ float s_b[G3];
    __shared__ float s_xn[HH];

    int j   = threadIdx.x;
    int b   = blockIdx.x >> 1;
    int dir = blockIdx.x & 1;

    const float* whh = dir ? whh_b : whh_f;
    float bhh = (dir ? bhh_b : bhh_f)[j];

    unsigned long long w[64];
    const unsigned long long* wp =
        (const unsigned long long*)(whh + (size_t)j * HH);
#pragma unroll
    for (int i = 0; i < 64; i++) w[i] = wp[i];

    if (j < HH) s_h[j] = 0.f;
    float hreg = 0.f;

    long long tokbase = (long long)b * SS;
    int t0 = dir ? (SS - 1) : 0;
    long long gstr = dir ? -768 : 768;
    long long hstr = dir ? -256 : 256;

    const float* gp = g_gx + (tokbase + t0) * 768 + (long long)dir * G3 + j;
    float*       hp = g_hio + (tokbase + t0) * 256 + (long long)dir * HH + j;

    float gx_n1 = gp[0];
    gp += gstr;
    float gx_n2 = gp[0];
    __syncthreads();

    for (int tt = 0; tt < SS; tt++) {
        float gxv = gx_n1;
        gx_n1 = gx_n2;
        gp += gstr;
        if (tt + 2 < SS) gx_n2 = *gp;           // 2-step-ahead prefetch

        unsigned long long a0 = 0ull, a1 = 0ull;
        const ulonglong2* hv = (const ulonglong2*)s_h;
#pragma unroll
        for (int k = 0; k < 32; k++) {
            ulonglong2 hk = hv[k];               // LDS.128, warp-uniform broadcast
            a0 = ffma2(w[2 * k],     hk.x, a0);
            a1 = ffma2(w[2 * k + 1], hk.y, a1);
        }
        float2 f0 = unpk(a0), f1 = unpk(a1);
        float gh = (f0.x + f0.y) + (f1.x + f1.y) + bhh;

        if (j < 2 * HH) {
            s_b[j] = gh + gxv;                   // r,z rows: pre-added
        } else {
            s_b[j] = gh;                         // n rows: keep hn separate
            s_xn[j - 2 * HH] = gxv;
        }
        __syncthreads();

        if (j < HH) {
            float r = sigf(s_b[j]);
            float z = sigf(s_b[HH + j]);
            float n = tanhfast(fmaf(r, s_b[2 * HH + j], s_xn[j]));
            hreg = fmaf(z, hreg - n, n);         // (1-z)*n + z*h
            s_h[j] = hreg;
            *hp = hreg;
            hp += hstr;
        }
        __syncthreads();
    }
}

// ---------------- layer-1 GEMM via mma.sync (bf16 3-term split) ----------------
// C[262144 x 768] = A[262144 x 256] * W[768 x 256]^T + bias
// CTA tile M=128, N=256 (grid.y = 3), 8 warps as 2x4 (warp tile 64x64),
// K in 16 chunks of 16. DOUBLE-BUFFERED smem (2 stages), 1 barrier per chunk:
//   iter ck: STS chunk ck+1 -> idle stage; LDG chunk ck+2 -> regs;
//            ldmatrix+mma on current stage; __syncthreads.
#define ASTR 24            // smem row stride in bf16 (48B: aligned, conflict-free)
#define A_BYTES  (128 * ASTR * 2)              // 6144
#define B_BYTES  (256 * ASTR * 2)              // 12288
#define STG_AH   0
#define STG_AL   (A_BYTES)                     // 6144
#define STG_BH   (2 * A_BYTES)                 // 12288
#define STG_BL   (2 * A_BYTES + B_BYTES)       // 24576
#define STG_SZ   (2 * A_BYTES + 2 * B_BYTES)   // 36864
#define SMEM_TOT (2 * STG_SZ)                  // 73728

__device__ __forceinline__ void split_bf16(float4 v, uint2& hi, uint2& lo) {
    __nv_bfloat16 hx = __float2bfloat16(v.x), hy = __float2bfloat16(v.y);
    __nv_bfloat16 hz = __float2bfloat16(v.z), hw = __float2bfloat16(v.w);
    __nv_bfloat162 h01 = __halves2bfloat162(hx, hy);
    __nv_bfloat162 h23 = __halves2bfloat162(hz, hw);
    __nv_bfloat162 l01 = __halves2bfloat162(
        __float2bfloat16(v.x - __bfloat162float(hx)),
        __float2bfloat16(v.y - __bfloat162float(hy)));
    __nv_bfloat162 l23 = __halves2bfloat162(
        __float2bfloat16(v.z - __bfloat162float(hz)),
        __float2bfloat16(v.w - __bfloat162float(hw)));
    hi = make_uint2(*(uint32_t*)&h01, *(uint32_t*)&h23);
    lo = make_uint2(*(uint32_t*)&l01, *(uint32_t*)&l23);
}

__global__ void __launch_bounds__(256, 1) k_gemm_tc(
    const float* __restrict__ Wf, const float* __restrict__ bf,
    const float* __restrict__ Wb, const float* __restrict__ bb) {
    extern __shared__ __align__(16) char smem[];
    uint32_t sb = smem_u32(smem);

    int tid = threadIdx.x, wid = tid >> 5, lane = tid & 31;
    long long m0 = (long long)blockIdx.x * 128;
    int n0 = blockIdx.y * 256;
    int wm = wid >> 2, wn = wid & 3;             // warp 64x64 tile

    // ldmatrix per-lane offsets (bytes, within a stage)
    uint32_t aoff = (uint32_t)(((wm * 64 + (lane & 15)) * ASTR + (lane >> 4) * 8) * 2);
    uint32_t boff = (uint32_t)(((wn * 64 + (lane & 7) + ((lane >> 4) << 3)) * ASTR
                                + ((lane >> 3) & 1) * 8) * 2);

    // STS per-thread targets (2 A rows, 4 B rows worth of float4 tasks)
    int arow[2], ac4[2], brow[4], bc4[4];
    const float* bsrc[4];
#pragma unroll
    for (int i = 0; i < 2; i++) {
        int task = tid + i * 256;
        arow[i] = task >> 2; ac4[i] = task & 3;
    }
#pragma unroll
    for (int i = 0; i < 4; i++) {
        int task = tid + i * 256;
        brow[i] = task >> 2; bc4[i] = task & 3;
        int n = n0 + brow[i];
        bsrc[i] = (n < 384) ? (Wf + (size_t)n * 256) : (Wb + (size_t)(n - 384) * 256);
    }

    float acc[4][8][4];
#pragma unroll
    for (int i = 0; i < 4; i++)
#pragma unroll
        for (int j = 0; j < 8; j++)
#pragma unroll
            for (int q = 0; q < 4; q++) acc[i][j][q] = 0.f;

    float4 pA[2], pB[4];
    // fetch chunk 0
#pragma unroll
    for (int i = 0; i < 2; i++)
        pA[i] = *(const float4*)(g_hio + (m0 + arow[i]) * 256 + ac4[i] * 4);
#pragma unroll
    for (int i = 0; i < 4; i++)
        pB[i] = *(const float4*)(bsrc[i] + bc4[i] * 4);

    // store chunk 0 -> stage 0
#pragma unroll
    for (int i = 0; i < 2; i++) {
        uint2 hi, lo; split_bf16(pA[i], hi, lo);
        uint32_t off = (uint32_t)((arow[i] * ASTR + ac4[i] * 4) * 2);
        *(uint2*)(smem + STG_AH + off) = hi;
        *(uint2*)(smem + STG_AL + off) = lo;
    }
#pragma unroll
    for (int i = 0; i < 4; i++) {
        uint2 hi, lo; split_bf16(pB[i], hi, lo);
        uint32_t off = (uint32_t)((brow[i] * ASTR + bc4[i] * 4) * 2);
        *(uint2*)(smem + STG_BH + off) = hi;
        *(uint2*)(smem + STG_BL + off) = lo;
    }
    // fetch chunk 1
#pragma unroll
    for (int i = 0; i < 2; i++)
        pA[i] = *(const float4*)(g_hio + (m0 + arow[i]) * 256 + 16 + ac4[i] * 4);
#pragma unroll
    for (int i = 0; i < 4; i++)
        pB[i] = *(const float4*)(bsrc[i] + 16 + bc4[i] * 4);
    __syncthreads();

    for (int ck = 0; ck < 16; ck++) {
        uint32_t cur = (uint32_t)(ck & 1) * STG_SZ;
        uint32_t nxt = (uint32_t)((ck + 1) & 1) * STG_SZ;

        // ---- STS chunk ck+1 into idle stage (no barrier needed: stage was
        //      last read in iter ck-1, separated by that iter's barrier) ----
        if (ck + 1 < 16) {
#pragma unroll
            for (int i = 0; i < 2; i++) {
                uint2 hi, lo; split_bf16(pA[i], hi, lo);
                uint32_t off = nxt + (uint32_t)((arow[i] * ASTR + ac4[i] * 4) * 2);
                *(uint2*)(smem + STG_AH + off) = hi;
                *(uint2*)(smem + STG_AL + off) = lo;
            }
#pragma unroll
            for (int i = 0; i < 4; i++) {
                uint2 hi, lo; split_bf16(pB[i], hi, lo);
                uint32_t off = nxt + (uint32_t)((brow[i] * ASTR + bc4[i] * 4) * 2);
                *(uint2*)(smem + STG_BH + off) = hi;
                *(uint2*)(smem + STG_BL + off) = lo;
            }
        }
        // ---- LDG chunk ck+2 (lands during this iter's MMAs + next STS) ----
        if (ck + 2 < 16) {
            int kc = (ck + 2) * 16;
#pragma unroll
            for (int i = 0; i < 2; i++)
                pA[i] = *(const float4*)(g_hio + (m0 + arow[i]) * 256 + kc + ac4[i] * 4);
#pragma unroll
            for (int i = 0; i < 4; i++)
                pB[i] = *(const float4*)(bsrc[i] + kc + bc4[i] * 4);
        }

        // ---- ldmatrix + mma on current stage: (Ah,Bh), (Ah,Bl), (Al,Bh) ----
        uint32_t ah_a = sb + cur + STG_AH + aoff, al_a = sb + cur + STG_AL + aoff;
        uint32_t bh_a = sb + cur + STG_BH + boff, bl_a = sb + cur + STG_BL + boff;
#pragma unroll
        for (int term = 0; term < 3; term++) {
            uint32_t aAddr = (term == 2) ? al_a : ah_a;
            uint32_t bAddr = (term == 1) ? bl_a : bh_a;
            uint32_t afr[4][4];
#pragma unroll
            for (int mf = 0; mf < 4; mf++)
                ldmx4(afr[mf][0], afr[mf][1], afr[mf][2], afr[mf][3],
                      aAddr + mf * (16 * ASTR * 2));
            uint32_t bfr[8][2];
#pragma unroll
            for (int p = 0; p < 4; p++) {
                uint32_t r0, r1, r2, r3;
                ldmx4(r0, r1, r2, r3, bAddr + p * (16 * ASTR * 2));
                bfr[2 * p][0] = r0; bfr[2 * p][1] = r1;
                bfr[2 * p + 1][0] = r2; bfr[2 * p + 1][1] = r3;
            }
#pragma unroll
            for (int mf = 0; mf < 4; mf++)
#pragma unroll
                for (int nf = 0; nf < 8; nf++)
                    mma_bf16(acc[mf][nf], afr[mf], bfr[nf]);
        }
        __syncthreads();
    }

    // ---- epilogue: acc + bias -> g_gx ----
    int g = lane >> 2, c2 = (lane & 3) * 2;
    float bias2[8][2];
#pragma unroll
    for (int nf = 0; nf < 8; nf++) {
        int col = n0 + wn * 64 + nf * 8 + c2;
        bias2[nf][0] = (col < 384) ? bf[col] : bb[col - 384];
        bias2[nf][1] = (col + 1 < 384) ? bf[col + 1] : bb[col + 1 - 384];
    }
#pragma unroll
    for (int mf = 0; mf < 4; mf++) {
        long long r0 = m0 + wm * 64 + mf * 16 + g;
#pragma unroll
        for (int nf = 0; nf < 8; nf++) {
            int col = n0 + wn * 64 + nf * 8 + c2;
            *(float2*)&g_gx[r0 * 768 + col] =
                make_float2(acc[mf][nf][0] + bias2[nf][0],
                            acc[mf][nf][1] + bias2[nf][1]);
            *(float2*)&g_gx[(r0 + 8) * 768 + col] =
                make_float2(acc[mf][nf][2] + bias2[nf][0],
                            acc[mf][nf][3] + bias2[nf][1]);
        }
    }
}

// ---------------- output head: logits = h1out @ wout^T + bout -----------------
__global__ void k_head(const float* __restrict__ wout,
                       const float* __restrict__ bout,
                       float* __restrict__ out) {
    int warp = threadIdx.x >> 5, lane = threadIdx.x & 31;
    long long token = (long long)blockIdx.x * 8 + warp;
    const float* hrow = g_hio + token * 256;
    float acc = 0.f;
#pragma unroll
    for (int i = 0; i < 8; i++) {
        int c = lane + i * 32;
        acc = fmaf(hrow[c], wout[c], acc);
    }
#pragma unroll
    for (int off = 16; off; off >>= 1)
        acc += __shfl_xor_sync(0xffffffffu, acc, off);
    if (lane == 0) out[token] = acc + bout[0];
}

// ---------------- launch ------------------------------------------------------
extern "C" void kernel_launch(void* const* d_in, const int* in_sizes, int n_in,
                              void* d_out, int out_size) {
    const float* x     = (const float*)d_in[0];
    const float* wih0f = (const float*)d_in[1];
    const float* whh0f = (const float*)d_in[2];
    const float* bih0f = (const float*)d_in[3];
    const float* bhh0f = (const float*)d_in[4];
    const float* wih0b = (const float*)d_in[5];
    const float* whh0b = (const float*)d_in[6];
    const float* bih0b = (const float*)d_in[7];
    const float* bhh0b = (const float*)d_in[8];
    const float* wih1f = (const float*)d_in[9];
    const float* whh1f = (const float*)d_in[10];
    const float* bih1f = (const float*)d_in[11];
    const float* bhh1f = (const float*)d_in[12];
    const float* wih1b = (const float*)d_in[13];
    const float* whh1b = (const float*)d_in[14];
    const float* bih1b = (const float*)d_in[15];
    const float* bhh1b = (const float*)d_in[16];
    const float* wout  = (const float*)d_in[17];
    const float* bout  = (const float*)d_in[18];
    float* out = (float*)d_out;

    static bool attr_done = false;
    if (!attr_done) {
        cudaFuncSetAttribute(k_gemm_tc,
                             cudaFuncAttributeMaxDynamicSharedMemorySize, SMEM_TOT);
        attr_done = true;
    }

    k_gx0    <<<NTOK / 8, 768>>>(x, wih0f, bih0f, wih0b, bih0b);
    k_rec    <<<128, 384>>>(whh0f, bhh0f, whh0b, bhh0b);
    k_gemm_tc<<<dim3(2048, 3), 256, SMEM_TOT>>>(wih1f, bih1f, wih1b, bih1b);
    k_rec    <<<128, 384>>>(whh1f, bhh1f, whh1b, bhh1b);
    k_head   <<<NTOK / 8, 256>>>(wout, bout, out);
}